// round 8
// baseline (speedup 1.0000x reference)
#include <cuda_runtime.h>
#include <cstdint>

// ---------------- problem constants ----------------
#define T_TOK   16384
#define D_DIM   2048
#define E_EXP   64
#define AUX_W   0.01f

#define BM      128
#define BK      32
#define NCHUNK  (D_DIM / BK)      // 64
#define THREADS 512
#define NCTA    (T_TOK / BM)      // 128
#define LPAD    68

// row stride 320 B: 32 k-elements x 8 B (hi,lo interleaved in 16-B units) + 64 pad
#define ROW_B   320
#define A_OFF   0
#define B_OFF   (BM * ROW_B)              // 40960
#define STG_B   (B_OFF + E_EXP * ROW_B)   // 61440
#define NSTG    3
#define DYN_SMEM (NSTG * STG_B)           // 184320

// ---------------- global scratch ----------------
__device__ uint4    g_Wpk[E_EXP * NCHUNK * 16];   // [e][chunk][unit] 16-B units
__device__ float    g_psum[NCTA * E_EXP];
__device__ float    g_pcnt[NCTA * E_EXP];
__device__ unsigned g_done = 0;

// ---------------- helpers ----------------
__device__ __forceinline__ uint32_t smem_u32(const void* p) {
    uint32_t a;
    asm("{ .reg .u64 t; cvta.to.shared.u64 t, %1; cvt.u32.u64 %0, t; }" : "=r"(a) : "l"(p));
    return a;
}
__device__ __forceinline__ void cvt_hilo(float x, uint32_t& hi, uint32_t& lo) {
    uint32_t h;
    asm("cvt.rna.tf32.f32 %0, %1;" : "=r"(h) : "f"(x));
    float r = x - __uint_as_float(h);
    uint32_t l;
    asm("cvt.rna.tf32.f32 %0, %1;" : "=r"(l) : "f"(r));
    hi = h; lo = l;
}
__device__ __forceinline__ void sts64(uint32_t addr, uint32_t a, uint32_t b) {
    asm volatile("st.shared.v2.b32 [%0], {%1, %2};" :: "r"(addr), "r"(a), "r"(b) : "memory");
}
__device__ __forceinline__ uint4 lds128(uint32_t addr) {
    uint4 r;
    asm volatile("ld.shared.v4.b32 {%0,%1,%2,%3}, [%4];"
        : "=r"(r.x), "=r"(r.y), "=r"(r.z), "=r"(r.w) : "r"(addr));
    return r;
}
#define CP_ASYNC16(saddr, gptr) \
    asm volatile("cp.async.cg.shared.global [%0], [%1], 16;" :: "r"(saddr), "l"(gptr) : "memory")
#define CP_COMMIT() asm volatile("cp.async.commit_group;" ::: "memory")
#define CP_WAIT(n)  asm volatile("cp.async.wait_group %0;" :: "n"(n) : "memory")

#define MMA_TF32(c, a, b) \
    asm volatile("mma.sync.aligned.m16n8k8.row.col.f32.tf32.tf32.f32 " \
        "{%0,%1,%2,%3}, {%4,%5,%6,%7}, {%8,%9}, {%0,%1,%2,%3};" \
        : "+f"((c)[0]), "+f"((c)[1]), "+f"((c)[2]), "+f"((c)[3]) \
        : "r"((a)[0]), "r"((a)[1]), "r"((a)[2]), "r"((a)[3]), "r"((b)[0]), "r"((b)[1]))

// ---------------- W pre-pack: [e][chunk][unit] ----------------
// unit u of chunk c holds k0 = (u>>2)*8 + (u&3), k1 = k0+4 (local to chunk):
//   {hi(k0), lo(k0), hi(k1), lo(k1)}
__global__ __launch_bounds__(256) void prep_kernel(const float* __restrict__ W) {
    int i = blockIdx.x * 256 + threadIdx.x;          // 0 .. 65535
    int u = i & 15;
    int c = (i >> 4) & (NCHUNK - 1);
    int e = i >> 10;
    int k0 = c * BK + ((u >> 2) * 8 + (u & 3));
    float w0 = W[e * D_DIM + k0];
    float w1 = W[e * D_DIM + k0 + 4];
    uint32_t h0, l0, h1, l1;
    cvt_hilo(w0, h0, l0);
    cvt_hilo(w1, h1, l1);
    g_Wpk[i] = make_uint4(h0, l0, h1, l1);
}

// ---------------- router ----------------
extern __shared__ __align__(16) float Sf[];

__global__ __launch_bounds__(THREADS, 1) void router_kernel(
    const float* __restrict__ X,
    const float* __restrict__ W,
    float* __restrict__ out)
{
    __shared__ int   sCnt[E_EXP];
    __shared__ float sRed[E_EXP];
    __shared__ unsigned s_last;

    const int tid   = threadIdx.x;
    const int lane  = tid & 31;
    const int wrp   = tid >> 5;       // 0..15
    const int warpM = wrp >> 2;       // 0..3 -> rows [warpM*32, +32)
    const int warpN = wrp & 3;        // 0..3 -> cols [warpN*16, +16)
    const int quad  = lane >> 2;
    const int qt    = lane & 3;
    const int bid   = blockIdx.x;
    const int m0    = bid * BM;

    if (tid < E_EXP) sCnt[tid] = 0;

    const float* Xp = X + (size_t)m0 * D_DIM;
    const uint32_t sb = smem_u32(Sf);

    // A producer slots: idx = tid + r*512 (r<2): row = idx>>3, c4 = idx&7
    int ar[2], ac[2];
#pragma unroll
    for (int r = 0; r < 2; r++) { int s = tid + r * THREADS; ar[r] = s >> 3; ac[r] = s & 7; }
    // B cp.async slots: idx = tid + r*512: e = idx>>4, u = idx&15
    int be[2], bu[2];
#pragma unroll
    for (int r = 0; r < 2; r++) { int s = tid + r * THREADS; be[r] = s >> 4; bu[r] = s & 15; }

    float4 xv[2];
    auto ldgx = [&](int i) {
        const int kt = i * BK;
#pragma unroll
        for (int r = 0; r < 2; r++) xv[r] = *(const float4*)(Xp + (size_t)ar[r] * D_DIM + kt + ac[r] * 4);
    };
    auto stsa = [&](int stg) {
        const uint32_t st = sb + (uint32_t)stg * STG_B + A_OFF;
#pragma unroll
        for (int r = 0; r < 2; r++) {
            uint32_t base = st + (uint32_t)ar[r] * ROW_B + (uint32_t)(ac[r] >> 1) * 64u + (uint32_t)(ac[r] & 1) * 8u;
            const float* v = (const float*)&xv[r];
#pragma unroll
            for (int j = 0; j < 4; j++) {
                uint32_t h, l; cvt_hilo(v[j], h, l);
                sts64(base + (uint32_t)j * 16u, h, l);
            }
        }
    };
    auto cpb = [&](int i, int stg) {
        const uint32_t st = sb + (uint32_t)stg * STG_B + B_OFF;
#pragma unroll
        for (int r = 0; r < 2; r++) {
            const uint4* src = g_Wpk + ((size_t)be[r] * NCHUNK + i) * 16 + bu[r];
            uint32_t dst = st + (uint32_t)be[r] * ROW_B + (uint32_t)bu[r] * 16u;
            CP_ASYNC16(dst, src);
        }
        CP_COMMIT();
    };

    float acc[2][2][4];
#pragma unroll
    for (int mi = 0; mi < 2; mi++)
#pragma unroll
        for (int ni = 0; ni < 2; ni++)
#pragma unroll
            for (int r = 0; r < 4; r++) acc[mi][ni][r] = 0.0f;

    // ---- prologue ----
    ldgx(0);
    stsa(0);
    cpb(0, 0);
    cpb(1, 1);
    ldgx(1);
    CP_WAIT(1);          // chunk 0's B done; chunk 1 in flight
    __syncthreads();

    const uint32_t aBase0 = (uint32_t)(warpM * 32 + quad) * ROW_B + A_OFF;
    const uint32_t bBase0 = (uint32_t)(warpN * 16 + quad) * ROW_B + B_OFF;
    const uint32_t qoff   = (uint32_t)qt * 16u;

#pragma unroll 1
    for (int i = 0; i < NCHUNK; i++) {
        const uint32_t st = sb + (uint32_t)(i % NSTG) * STG_B;

        // producers (2-deep)
        if (i + 2 < NCHUNK) cpb(i + 2, (i + 2) % NSTG);
        if (i + 1 < NCHUNK) { stsa((i + 1) % NSTG); }
        if (i + 2 < NCHUNK) ldgx(i + 2);

        // consumer: chunk i
#pragma unroll
        for (int k8 = 0; k8 < 4; k8++) {
            const uint32_t off = (uint32_t)k8 * 64u + qoff;
            uint4 A0 = lds128(st + aBase0 + off);
            uint4 A1 = lds128(st + aBase0 + 8u * ROW_B + off);
            uint4 A2 = lds128(st + aBase0 + 16u * ROW_B + off);
            uint4 A3 = lds128(st + aBase0 + 24u * ROW_B + off);
            uint4 B0 = lds128(st + bBase0 + off);
            uint4 B1 = lds128(st + bBase0 + 8u * ROW_B + off);

            uint32_t ahi[2][4] = {{A0.x, A1.x, A0.z, A1.z}, {A2.x, A3.x, A2.z, A3.z}};
            uint32_t alo[2][4] = {{A0.y, A1.y, A0.w, A1.w}, {A2.y, A3.y, A2.w, A3.w}};
            uint32_t bhi[2][2] = {{B0.x, B0.z}, {B1.x, B1.z}};
            uint32_t blo[2][2] = {{B0.y, B0.w}, {B1.y, B1.w}};

#pragma unroll
            for (int mi = 0; mi < 2; mi++)
#pragma unroll
                for (int ni = 0; ni < 2; ni++) MMA_TF32(acc[mi][ni], ahi[mi], bhi[ni]);
#pragma unroll
            for (int mi = 0; mi < 2; mi++)
#pragma unroll
                for (int ni = 0; ni < 2; ni++) MMA_TF32(acc[mi][ni], ahi[mi], blo[ni]);
#pragma unroll
            for (int mi = 0; mi < 2; mi++)
#pragma unroll
                for (int ni = 0; ni < 2; ni++) MMA_TF32(acc[mi][ni], alo[mi], bhi[ni]);
        }

        if (i + 2 < NCHUNK)      CP_WAIT(1);
        else                     CP_WAIT(0);
        __syncthreads();
    }

    // ---------- write logits to smem [128][LPAD] ----------
#pragma unroll
    for (int mi = 0; mi < 2; mi++)
#pragma unroll
        for (int ni = 0; ni < 2; ni++) {
            int row = warpM * 32 + mi * 16 + quad;
            int col = warpN * 16 + ni * 8 + 2 * qt;
            *(float2*)&Sf[row * LPAD + col]       = make_float2(acc[mi][ni][0], acc[mi][ni][1]);
            *(float2*)&Sf[(row + 8) * LPAD + col] = make_float2(acc[mi][ni][2], acc[mi][ni][3]);
        }
    __syncthreads();

    // ---------- per-token epilogue (threads 0..127) ----------
    const bool act = tid < BM;
    float v[E_EXP];
    float l1 = -1e30f, l2 = -1e30f, inv = 0.0f;
    int   i1 = 0, i2 = 0;
    if (act) {
        const float* row = &Sf[tid * LPAD];
#pragma unroll
        for (int j = 0; j < E_EXP / 4; j++) {
            float4 q = *(const float4*)&row[4 * j];
            v[4 * j] = q.x; v[4 * j + 1] = q.y; v[4 * j + 2] = q.z; v[4 * j + 3] = q.w;
        }
#pragma unroll
        for (int e = 0; e < E_EXP; e++) {
            float x = v[e];
            if (x > l1)      { l2 = l1; i2 = i1; l1 = x; i1 = e; }
            else if (x > l2) { l2 = x;  i2 = e; }
        }
        float ssum = 0.0f;
#pragma unroll
        for (int e = 0; e < E_EXP; e++) { float p = __expf(v[e] - l1); ssum += p; v[e] = p; }
        inv = 1.0f / ssum;
    }
    __syncthreads();
    if (act) {
#pragma unroll
        for (int j = 0; j < E_EXP / 4; j++) {
            float4 q = make_float4(v[4 * j] * inv, v[4 * j + 1] * inv, v[4 * j + 2] * inv, v[4 * j + 3] * inv);
            *(float4*)&Sf[tid * E_EXP + 4 * j] = q;
        }
        float e2 = __expf(l2 - l1);
        float dn = 1.0f / (1.0f + e2);
        int gm = m0 + tid;
        out[2 * gm + 0] = (float)i1;
        out[2 * gm + 1] = (float)i2;
        out[2 * T_TOK + 2 * gm + 0] = dn;
        out[2 * T_TOK + 2 * gm + 1] = e2 * dn;
        atomicAdd(&sCnt[i1], 1);
    }
    __syncthreads();

    // ---------- per-expert partials + fused aux ----------
    if (tid < E_EXP) {
        float s = 0.0f;
#pragma unroll 8
        for (int m = 0; m < BM; m++) s += Sf[m * E_EXP + tid];
        g_psum[bid * E_EXP + tid] = s;
        g_pcnt[bid * E_EXP + tid] = (float)sCnt[tid];
    }
    __threadfence();
    __syncthreads();

    if (tid == 0) s_last = (atomicInc(&g_done, NCTA - 1) == NCTA - 1) ? 1u : 0u;
    __syncthreads();

    if (s_last) {
        __threadfence();
        if (tid < E_EXP) {
            float a = 0.0f, cn = 0.0f;
#pragma unroll 8
            for (int b = 0; b < NCTA; b++) {
                a  += __ldcg(&g_psum[b * E_EXP + tid]);
                cn += __ldcg(&g_pcnt[b * E_EXP + tid]);
            }
            float invT = 1.0f / (float)T_TOK;
            sRed[tid] = (cn * invT) * (a * invT);
        }
        __syncthreads();
        if (tid < 32) {
            float vv = sRed[tid] + sRed[tid + 32];
#pragma unroll
            for (int o = 16; o > 0; o >>= 1) vv += __shfl_xor_sync(0xFFFFFFFF, vv, o);
            if (tid == 0) out[4 * T_TOK] = (float)E_EXP * AUX_W * vv;
        }
    }
}

extern "C" void kernel_launch(void* const* d_in, const int* in_sizes, int n_in,
                              void* d_out, int out_size) {
    const float* X = (const float*)d_in[0];
    const float* W = (const float*)d_in[1];
    float* out = (float*)d_out;

    prep_kernel<<<256, 256>>>(W);
    cudaFuncSetAttribute(router_kernel, cudaFuncAttributeMaxDynamicSharedMemorySize, DYN_SMEM);
    router_kernel<<<NCTA, THREADS, DYN_SMEM>>>(X, W, out);
}

// round 10
// speedup vs baseline: 1.4884x; 1.4884x over previous
#include <cuda_runtime.h>
#include <cstdint>

// ---------------- problem constants ----------------
#define T_TOK   16384
#define D_DIM   2048
#define E_EXP   64
#define AUX_W   0.01f

#define BM      128
#define BK      32
#define NCHUNK  (D_DIM / BK)      // 64
#define THREADS 256
#define NCTA    (T_TOK / BM)      // 128
#define LPAD    68

// smem stage layout (bytes). bf16 planes, row stride 80 B (rows of 32 bf16 = 64 B + 16 pad)
// A planes: 128 rows x 80 = 10240 each; B planes: 64 rows x 80 = 5120 each
#define AP0     0
#define AP1     10240
#define AP2     20480
#define BP0     30720
#define BP1     35840
#define BP2     40960
#define STG_B   46080
#define DYN_SMEM (2 * STG_B)      // 92160

// ---------------- global scratch ----------------
// W pre-split into 3 bf16 planes, pair-packed u32: [e][k/2] (k ascending in pair)
__device__ uint32_t g_Wb0[E_EXP * D_DIM / 2];
__device__ uint32_t g_Wb1[E_EXP * D_DIM / 2];
__device__ uint32_t g_Wb2[E_EXP * D_DIM / 2];
__device__ float    g_psum[NCTA * E_EXP];
__device__ float    g_pcnt[NCTA * E_EXP];
__device__ unsigned g_done = 0;

// ---------------- helpers ----------------
__device__ __forceinline__ uint32_t smem_u32(const void* p) {
    uint32_t a;
    asm("{ .reg .u64 t; cvta.to.shared.u64 t, %1; cvt.u32.u64 %0, t; }" : "=r"(a) : "l"(p));
    return a;
}
// round-to-nearest 3-way bf16 split of a float pair (x = even k -> low half)
__device__ __forceinline__ void split3_pair(float x, float y, uint32_t& p0, uint32_t& p1, uint32_t& p2) {
    asm("cvt.rn.bf16x2.f32 %0, %1, %2;" : "=r"(p0) : "f"(y), "f"(x));
    float x0 = __uint_as_float(p0 << 16);
    float y0 = __uint_as_float(p0 & 0xFFFF0000u);
    float xr1 = x - x0;
    float yr1 = y - y0;
    asm("cvt.rn.bf16x2.f32 %0, %1, %2;" : "=r"(p1) : "f"(yr1), "f"(xr1));
    float x1 = __uint_as_float(p1 << 16);
    float y1 = __uint_as_float(p1 & 0xFFFF0000u);
    float xr2 = xr1 - x1;
    float yr2 = yr1 - y1;
    asm("cvt.rn.bf16x2.f32 %0, %1, %2;" : "=r"(p2) : "f"(yr2), "f"(xr2));
}
__device__ __forceinline__ void sts64(uint32_t addr, uint32_t a, uint32_t b) {
    asm volatile("st.shared.v2.b32 [%0], {%1, %2};" :: "r"(addr), "r"(a), "r"(b) : "memory");
}
__device__ __forceinline__ uint32_t lds32(uint32_t addr) {
    uint32_t r;
    asm volatile("ld.shared.b32 %0, [%1];" : "=r"(r) : "r"(addr));
    return r;
}
#define CP_ASYNC16(saddr, gptr) \
    asm volatile("cp.async.cg.shared.global [%0], [%1], 16;" :: "r"(saddr), "l"(gptr) : "memory")
#define CP_COMMIT() asm volatile("cp.async.commit_group;" ::: "memory")
#define CP_WAIT0()  asm volatile("cp.async.wait_group 0;" ::: "memory")

#define MMA_BF16(c, a0, a1, a2, a3, b0, b1) \
    asm volatile("mma.sync.aligned.m16n8k16.row.col.f32.bf16.bf16.f32 " \
        "{%0,%1,%2,%3}, {%4,%5,%6,%7}, {%8,%9}, {%0,%1,%2,%3};" \
        : "+f"((c)[0]), "+f"((c)[1]), "+f"((c)[2]), "+f"((c)[3]) \
        : "r"(a0), "r"(a1), "r"(a2), "r"(a3), "r"(b0), "r"(b1))

// ---------------- W pre-split kernel ----------------
__global__ __launch_bounds__(256) void prep_kernel(const float* __restrict__ W) {
    int i = blockIdx.x * 256 + threadIdx.x;     // 0..65535 pair index
    float2 v = ((const float2*)W)[i];
    uint32_t p0, p1, p2;
    split3_pair(v.x, v.y, p0, p1, p2);
    g_Wb0[i] = p0;
    g_Wb1[i] = p1;
    g_Wb2[i] = p2;
}

// ---------------- router ----------------
extern __shared__ __align__(16) float Sf[];

__global__ __launch_bounds__(THREADS, 1) void router_kernel(
    const float* __restrict__ X,
    const float* __restrict__ W,
    float* __restrict__ out)
{
    __shared__ int   sCnt[E_EXP];
    __shared__ float sRed[E_EXP];
    __shared__ unsigned s_last;

    const int tid   = threadIdx.x;
    const int lane  = tid & 31;
    const int wrp   = tid >> 5;
    const int warpM = wrp >> 1;       // 0..3 -> rows [warpM*32,+32)
    const int warpN = wrp & 1;        // 0..1 -> cols [warpN*32,+32)
    const int quad  = lane >> 2;
    const int qt    = lane & 3;
    const int bid   = blockIdx.x;
    const int m0    = bid * BM;

    if (tid < E_EXP) sCnt[tid] = 0;

    const float* Xp = X + (size_t)m0 * D_DIM;
    const uint32_t sb = smem_u32(Sf);

    // A slots: idx = tid + r*256 (r<4): row = idx>>3 (0..127), c4 = idx&7
    int ar[4], ac[4];
#pragma unroll
    for (int r = 0; r < 4; r++) { int s = tid + r * THREADS; ar[r] = s >> 3; ac[r] = s & 7; }
    // B cp slots: idx = tid + r*256 (r<3): plane = idx>>8, j = idx&255: n = j>>2, c16 = j&3
    int bp[3], bn[3], bc[3];
#pragma unroll
    for (int r = 0; r < 3; r++) { int s = tid + r * THREADS; bp[r] = s >> 8; bn[r] = (s & 255) >> 2; bc[r] = s & 3; }

    float4 xv[4];
    auto ldgx = [&](int i) {
        const int kt = i * BK;
#pragma unroll
        for (int r = 0; r < 4; r++) xv[r] = *(const float4*)(Xp + (size_t)ar[r] * D_DIM + kt + ac[r] * 4);
    };
    auto stsa = [&](int stg) {
        const uint32_t st = sb + (uint32_t)stg * STG_B;
#pragma unroll
        for (int r = 0; r < 4; r++) {
            uint32_t base = st + (uint32_t)ar[r] * 80u + (uint32_t)ac[r] * 8u;
            uint32_t q00, q01, q02, q10, q11, q12;
            split3_pair(xv[r].x, xv[r].y, q00, q01, q02);
            split3_pair(xv[r].z, xv[r].w, q10, q11, q12);
            sts64(base + AP0, q00, q10);
            sts64(base + AP1, q01, q11);
            sts64(base + AP2, q02, q12);
        }
    };
    auto cpb = [&](int i, int stg) {
        const uint32_t st = sb + (uint32_t)stg * STG_B;
#pragma unroll
        for (int r = 0; r < 3; r++) {
            const uint32_t* gsrc =
                (bp[r] == 0 ? g_Wb0 : (bp[r] == 1 ? g_Wb1 : g_Wb2))
                + (size_t)bn[r] * (D_DIM / 2) + i * (BK / 2) + bc[r] * 4;
            uint32_t dst = st + BP0 + (uint32_t)bp[r] * 5120u + (uint32_t)bn[r] * 80u + (uint32_t)bc[r] * 16u;
            CP_ASYNC16(dst, gsrc);
        }
        CP_COMMIT();
    };

    float acc[2][4][4];
#pragma unroll
    for (int mi = 0; mi < 2; mi++)
#pragma unroll
        for (int ni = 0; ni < 4; ni++)
#pragma unroll
            for (int r = 0; r < 4; r++) acc[mi][ni][r] = 0.0f;

    // ---- prologue ----
    ldgx(0);
    stsa(0);
    cpb(0, 0);
    ldgx(1);
    CP_WAIT0();
    __syncthreads();

    const uint32_t aRow = (uint32_t)(warpM * 32 + quad) * 80u + (uint32_t)qt * 4u;
    const uint32_t bRow = (uint32_t)(warpN * 32 + quad) * 80u + (uint32_t)qt * 4u + BP0;

#pragma unroll 1
    for (int i = 0; i < NCHUNK; i++) {
        const int s = i & 1;
        const uint32_t st = sb + (uint32_t)s * STG_B;

        // producers for chunk i+1 / i+2
        if (i + 1 < NCHUNK) { cpb(i + 1, s ^ 1); stsa(s ^ 1); }
        if (i + 2 < NCHUNK) ldgx(i + 2);

        // consumer: 4 k8-groups
#pragma unroll
        for (int g = 0; g < 4; g++) {
            const uint32_t off = (uint32_t)g * 16u;
            // A frags: planes 0,1,2 at rows r, r+8, for mi = 0,1 (row +16*mi)
            uint32_t a0[2], a1[2], a2[2], a3[2], a4[2], a5[2];
#pragma unroll
            for (int mi = 0; mi < 2; mi++) {
                uint32_t ab = st + aRow + (uint32_t)(mi * 16) * 80u + off;
                a0[mi] = lds32(ab + AP0);            // p0, r
                a1[mi] = lds32(ab + AP0 + 640u);     // p0, r+8
                a2[mi] = lds32(ab + AP1);            // p1, r
                a3[mi] = lds32(ab + AP1 + 640u);     // p1, r+8
                a4[mi] = lds32(ab + AP2);            // p2, r
                a5[mi] = lds32(ab + AP2 + 640u);     // p2, r+8
            }
            // B frags: planes 0,1,2 per ni
            uint32_t b0[4], b1[4], b2[4];
#pragma unroll
            for (int ni = 0; ni < 4; ni++) {
                uint32_t bb = st + bRow + (uint32_t)(ni * 8) * 80u + off;
                b0[ni] = lds32(bb);            // p0
                b1[ni] = lds32(bb + 5120u);    // p1
                b2[ni] = lds32(bb + 10240u);   // p2
            }
            // MMA1: [p0|p1] x [q0|q1] -> p0q0 + p1q1
#pragma unroll
            for (int mi = 0; mi < 2; mi++)
#pragma unroll
                for (int ni = 0; ni < 4; ni++)
                    MMA_BF16(acc[mi][ni], a0[mi], a1[mi], a2[mi], a3[mi], b0[ni], b1[ni]);
            // MMA2: [p0|p1] x [q1|q0] -> p0q1 + p1q0
#pragma unroll
            for (int mi = 0; mi < 2; mi++)
#pragma unroll
                for (int ni = 0; ni < 4; ni++)
                    MMA_BF16(acc[mi][ni], a0[mi], a1[mi], a2[mi], a3[mi], b1[ni], b0[ni]);
            // MMA3: [p2|p0] x [q0|q2] -> p2q0 + p0q2
#pragma unroll
            for (int mi = 0; mi < 2; mi++)
#pragma unroll
                for (int ni = 0; ni < 4; ni++)
                    MMA_BF16(acc[mi][ni], a4[mi], a5[mi], a0[mi], a1[mi], b0[ni], b2[ni]);
        }
        CP_WAIT0();
        __syncthreads();
    }

    // ---------- write logits to smem [128][LPAD] ----------
#pragma unroll
    for (int mi = 0; mi < 2; mi++)
#pragma unroll
        for (int ni = 0; ni < 4; ni++) {
            int row = warpM * 32 + mi * 16 + quad;
            int col = warpN * 32 + ni * 8 + 2 * qt;
            *(float2*)&Sf[row * LPAD + col]       = make_float2(acc[mi][ni][0], acc[mi][ni][1]);
            *(float2*)&Sf[(row + 8) * LPAD + col] = make_float2(acc[mi][ni][2], acc[mi][ni][3]);
        }
    __syncthreads();

    // ---------- per-token epilogue (threads 0..127) ----------
    const bool act = tid < BM;
    float v[E_EXP];
    float l1 = -1e30f, l2 = -1e30f, inv = 0.0f;
    int   i1 = 0, i2 = 0;
    if (act) {
        const float* row = &Sf[tid * LPAD];
#pragma unroll
        for (int j = 0; j < E_EXP / 4; j++) {
            float4 q = *(const float4*)&row[4 * j];
            v[4 * j] = q.x; v[4 * j + 1] = q.y; v[4 * j + 2] = q.z; v[4 * j + 3] = q.w;
        }
#pragma unroll
        for (int e = 0; e < E_EXP; e++) {
            float x = v[e];
            if (x > l1)      { l2 = l1; i2 = i1; l1 = x; i1 = e; }
            else if (x > l2) { l2 = x;  i2 = e; }
        }
        float ssum = 0.0f;
#pragma unroll
        for (int e = 0; e < E_EXP; e++) { float p = __expf(v[e] - l1); ssum += p; v[e] = p; }
        inv = 1.0f / ssum;
    }
    __syncthreads();
    if (act) {
#pragma unroll
        for (int j = 0; j < E_EXP / 4; j++) {
            float4 q = make_float4(v[4 * j] * inv, v[4 * j + 1] * inv, v[4 * j + 2] * inv, v[4 * j + 3] * inv);
            *(float4*)&Sf[tid * E_EXP + 4 * j] = q;
        }
        float e2 = __expf(l2 - l1);
        float dn = 1.0f / (1.0f + e2);
        int gm = m0 + tid;
        out[2 * gm + 0] = (float)i1;
        out[2 * gm + 1] = (float)i2;
        out[2 * T_TOK + 2 * gm + 0] = dn;
        out[2 * T_TOK + 2 * gm + 1] = e2 * dn;
        atomicAdd(&sCnt[i1], 1);
    }
    __syncthreads();

    // ---------- per-expert partials + fused aux ----------
    if (tid < E_EXP) {
        float s = 0.0f;
#pragma unroll 8
        for (int m = 0; m < BM; m++) s += Sf[m * E_EXP + tid];
        g_psum[bid * E_EXP + tid] = s;
        g_pcnt[bid * E_EXP + tid] = (float)sCnt[tid];
    }
    __threadfence();
    __syncthreads();

    if (tid == 0) s_last = (atomicInc(&g_done, NCTA - 1) == NCTA - 1) ? 1u : 0u;
    __syncthreads();

    if (s_last) {
        __threadfence();
        if (tid < E_EXP) {
            float a = 0.0f, cn = 0.0f;
#pragma unroll 8
            for (int b = 0; b < NCTA; b++) {
                a  += __ldcg(&g_psum[b * E_EXP + tid]);
                cn += __ldcg(&g_pcnt[b * E_EXP + tid]);
            }
            float invT = 1.0f / (float)T_TOK;
            sRed[tid] = (cn * invT) * (a * invT);
        }
        __syncthreads();
        if (tid < 32) {
            float vv = sRed[tid] + sRed[tid + 32];
#pragma unroll
            for (int o = 16; o > 0; o >>= 1) vv += __shfl_xor_sync(0xFFFFFFFF, vv, o);
            if (tid == 0) out[4 * T_TOK] = (float)E_EXP * AUX_W * vv;
        }
    }
}

extern "C" void kernel_launch(void* const* d_in, const int* in_sizes, int n_in,
                              void* d_out, int out_size) {
    const float* X = (const float*)d_in[0];
    const float* W = (const float*)d_in[1];
    float* out = (float*)d_out;

    prep_kernel<<<256, 256>>>(W);
    cudaFuncSetAttribute(router_kernel, cudaFuncAttributeMaxDynamicSharedMemorySize, DYN_SMEM);
    router_kernel<<<NCTA, THREADS, DYN_SMEM>>>(X, W, out);
}

// round 11
// speedup vs baseline: 1.4909x; 1.0017x over previous
#include <cuda_runtime.h>
#include <cstdint>

// ---------------- problem constants ----------------
#define T_TOK   16384
#define D_DIM   2048
#define E_EXP   64
#define AUX_W   0.01f

#define BM      128
#define BK      32
#define NCHUNK  (D_DIM / BK)      // 64
#define THREADS 256
#define NCTA    (T_TOK / BM)      // 128
#define LPAD    68

// smem stage layout (bytes). bf16 planes, row stride 80 B (rows of 32 bf16 = 64 B + 16 pad)
// A planes: 128 rows x 80 = 10240 each; B planes: 64 rows x 80 = 5120 each
#define AP0     0
#define AP1     10240
#define AP2     20480
#define BP0     30720
#define BP1     35840
#define BP2     40960
#define STG_B   46080
#define NSTG    3
#define DYN_SMEM (NSTG * STG_B)   // 138240

// ---------------- global scratch ----------------
// W pre-split into 3 bf16 planes, pair-packed u32: [e][k/2] (k ascending in pair)
__device__ uint32_t g_Wb0[E_EXP * D_DIM / 2];
__device__ uint32_t g_Wb1[E_EXP * D_DIM / 2];
__device__ uint32_t g_Wb2[E_EXP * D_DIM / 2];
__device__ float    g_psum[NCTA * E_EXP];
__device__ float    g_pcnt[NCTA * E_EXP];
__device__ unsigned g_done = 0;

// ---------------- helpers ----------------
__device__ __forceinline__ uint32_t smem_u32(const void* p) {
    uint32_t a;
    asm("{ .reg .u64 t; cvta.to.shared.u64 t, %1; cvt.u32.u64 %0, t; }" : "=r"(a) : "l"(p));
    return a;
}
// round-to-nearest 3-way bf16 split of a float pair (x = even k -> low half)
__device__ __forceinline__ void split3_pair(float x, float y, uint32_t& p0, uint32_t& p1, uint32_t& p2) {
    asm("cvt.rn.bf16x2.f32 %0, %1, %2;" : "=r"(p0) : "f"(y), "f"(x));
    float x0 = __uint_as_float(p0 << 16);
    float y0 = __uint_as_float(p0 & 0xFFFF0000u);
    float xr1 = x - x0;
    float yr1 = y - y0;
    asm("cvt.rn.bf16x2.f32 %0, %1, %2;" : "=r"(p1) : "f"(yr1), "f"(xr1));
    float x1 = __uint_as_float(p1 << 16);
    float y1 = __uint_as_float(p1 & 0xFFFF0000u);
    float xr2 = xr1 - x1;
    float yr2 = yr1 - y1;
    asm("cvt.rn.bf16x2.f32 %0, %1, %2;" : "=r"(p2) : "f"(yr2), "f"(xr2));
}
__device__ __forceinline__ void sts64(uint32_t addr, uint32_t a, uint32_t b) {
    asm volatile("st.shared.v2.b32 [%0], {%1, %2};" :: "r"(addr), "r"(a), "r"(b) : "memory");
}
__device__ __forceinline__ uint32_t lds32(uint32_t addr) {
    uint32_t r;
    asm volatile("ld.shared.b32 %0, [%1];" : "=r"(r) : "r"(addr));
    return r;
}
#define CP_ASYNC16(saddr, gptr) \
    asm volatile("cp.async.cg.shared.global [%0], [%1], 16;" :: "r"(saddr), "l"(gptr) : "memory")
#define CP_COMMIT() asm volatile("cp.async.commit_group;" ::: "memory")
#define CP_WAIT(n)  asm volatile("cp.async.wait_group %0;" :: "n"(n) : "memory")

#define MMA_BF16(c, a0, a1, a2, a3, b0, b1) \
    asm volatile("mma.sync.aligned.m16n8k16.row.col.f32.bf16.bf16.f32 " \
        "{%0,%1,%2,%3}, {%4,%5,%6,%7}, {%8,%9}, {%0,%1,%2,%3};" \
        : "+f"((c)[0]), "+f"((c)[1]), "+f"((c)[2]), "+f"((c)[3]) \
        : "r"(a0), "r"(a1), "r"(a2), "r"(a3), "r"(b0), "r"(b1))

// ---------------- W pre-split kernel ----------------
__global__ __launch_bounds__(256) void prep_kernel(const float* __restrict__ W) {
    int i = blockIdx.x * 256 + threadIdx.x;     // 0..65535 pair index
    float2 v = ((const float2*)W)[i];
    uint32_t p0, p1, p2;
    split3_pair(v.x, v.y, p0, p1, p2);
    g_Wb0[i] = p0;
    g_Wb1[i] = p1;
    g_Wb2[i] = p2;
}

// ---------------- router ----------------
extern __shared__ __align__(16) float Sf[];

__global__ __launch_bounds__(THREADS, 1) void router_kernel(
    const float* __restrict__ X,
    const float* __restrict__ W,
    float* __restrict__ out)
{
    __shared__ int   sCnt[E_EXP];
    __shared__ float sRed[E_EXP];
    __shared__ unsigned s_last;

    const int tid   = threadIdx.x;
    const int lane  = tid & 31;
    const int wrp   = tid >> 5;
    const int warpM = wrp >> 1;       // 0..3 -> rows [warpM*32,+32)
    const int warpN = wrp & 1;        // 0..1 -> cols [warpN*32,+32)
    const int quad  = lane >> 2;
    const int qt    = lane & 3;
    const int bid   = blockIdx.x;
    const int m0    = bid * BM;

    if (tid < E_EXP) sCnt[tid] = 0;

    const float* Xp = X + (size_t)m0 * D_DIM;
    const uint32_t sb = smem_u32(Sf);

    // A slots: idx = tid + r*256 (r<4): row = idx>>3 (0..127), c4 = idx&7
    int ar[4], ac[4];
#pragma unroll
    for (int r = 0; r < 4; r++) { int s = tid + r * THREADS; ar[r] = s >> 3; ac[r] = s & 7; }
    // B cp slots: idx = tid + r*256 (r<3): plane = idx>>8, j = idx&255: n = j>>2, c16 = j&3
    int bp[3], bn[3], bc[3];
#pragma unroll
    for (int r = 0; r < 3; r++) { int s = tid + r * THREADS; bp[r] = s >> 8; bn[r] = (s & 255) >> 2; bc[r] = s & 3; }

    float4 xv[4];
    auto ldgx = [&](int i) {
        const int kt = i * BK;
#pragma unroll
        for (int r = 0; r < 4; r++) xv[r] = *(const float4*)(Xp + (size_t)ar[r] * D_DIM + kt + ac[r] * 4);
    };
    auto stsa = [&](int stg) {
        const uint32_t st = sb + (uint32_t)stg * STG_B;
#pragma unroll
        for (int r = 0; r < 4; r++) {
            uint32_t base = st + (uint32_t)ar[r] * 80u + (uint32_t)ac[r] * 8u;
            uint32_t q00, q01, q02, q10, q11, q12;
            split3_pair(xv[r].x, xv[r].y, q00, q01, q02);
            split3_pair(xv[r].z, xv[r].w, q10, q11, q12);
            sts64(base + AP0, q00, q10);
            sts64(base + AP1, q01, q11);
            sts64(base + AP2, q02, q12);
        }
    };
    auto cpb = [&](int i, int stg) {
        const uint32_t st = sb + (uint32_t)stg * STG_B;
#pragma unroll
        for (int r = 0; r < 3; r++) {
            const uint32_t* gsrc =
                (bp[r] == 0 ? g_Wb0 : (bp[r] == 1 ? g_Wb1 : g_Wb2))
                + (size_t)bn[r] * (D_DIM / 2) + i * (BK / 2) + bc[r] * 4;
            uint32_t dst = st + BP0 + (uint32_t)bp[r] * 5120u + (uint32_t)bn[r] * 80u + (uint32_t)bc[r] * 16u;
            CP_ASYNC16(dst, gsrc);
        }
        CP_COMMIT();
    };

    float acc[2][4][4];
#pragma unroll
    for (int mi = 0; mi < 2; mi++)
#pragma unroll
        for (int ni = 0; ni < 4; ni++)
#pragma unroll
            for (int r = 0; r < 4; r++) acc[mi][ni][r] = 0.0f;

    // ---- prologue: B two chunks deep, A one chunk deep in smem + one in regs ----
    ldgx(0);
    stsa(0);
    cpb(0, 0);
    cpb(1, 1);
    ldgx(1);            // xv = chunk 1, stored by stsa(1) in iter 0
    CP_WAIT(1);         // B chunk 0 resident; chunk 1 in flight
    __syncthreads();

    const uint32_t aRow = (uint32_t)(warpM * 32 + quad) * 80u + (uint32_t)qt * 4u;
    const uint32_t bRow = (uint32_t)(warpN * 32 + quad) * 80u + (uint32_t)qt * 4u + BP0;

#pragma unroll 1
    for (int i = 0; i < NCHUNK; i++) {
        const uint32_t st = sb + (uint32_t)(i % NSTG) * STG_B;

        // producers: A(i+1) from regs, A regs <- i+2, B(i+2) async
        if (i + 1 < NCHUNK) stsa((i + 1) % NSTG);
        if (i + 2 < NCHUNK) { ldgx(i + 2); cpb(i + 2, (i + 2) % NSTG); }

        // consumer: 4 k8-groups of chunk i
#pragma unroll
        for (int g = 0; g < 4; g++) {
            const uint32_t off = (uint32_t)g * 16u;
            uint32_t a0[2], a1[2], a2[2], a3[2], a4[2], a5[2];
#pragma unroll
            for (int mi = 0; mi < 2; mi++) {
                uint32_t ab = st + aRow + (uint32_t)(mi * 16) * 80u + off;
                a0[mi] = lds32(ab + AP0);            // p0, r
                a1[mi] = lds32(ab + AP0 + 640u);     // p0, r+8
                a2[mi] = lds32(ab + AP1);            // p1, r
                a3[mi] = lds32(ab + AP1 + 640u);     // p1, r+8
                a4[mi] = lds32(ab + AP2);            // p2, r
                a5[mi] = lds32(ab + AP2 + 640u);     // p2, r+8
            }
            uint32_t b0[4], b1[4], b2[4];
#pragma unroll
            for (int ni = 0; ni < 4; ni++) {
                uint32_t bb = st + bRow + (uint32_t)(ni * 8) * 80u + off;
                b0[ni] = lds32(bb);            // p0
                b1[ni] = lds32(bb + 5120u);    // p1
                b2[ni] = lds32(bb + 10240u);   // p2
            }
            // MMA1: [p0|p1] x [q0|q1] -> p0q0 + p1q1
#pragma unroll
            for (int mi = 0; mi < 2; mi++)
#pragma unroll
                for (int ni = 0; ni < 4; ni++)
                    MMA_BF16(acc[mi][ni], a0[mi], a1[mi], a2[mi], a3[mi], b0[ni], b1[ni]);
            // MMA2: [p0|p1] x [q1|q0] -> p0q1 + p1q0
#pragma unroll
            for (int mi = 0; mi < 2; mi++)
#pragma unroll
                for (int ni = 0; ni < 4; ni++)
                    MMA_BF16(acc[mi][ni], a0[mi], a1[mi], a2[mi], a3[mi], b1[ni], b0[ni]);
            // MMA3: [p2|p0] x [q0|q2] -> p2q0 + p0q2
#pragma unroll
            for (int mi = 0; mi < 2; mi++)
#pragma unroll
                for (int ni = 0; ni < 4; ni++)
                    MMA_BF16(acc[mi][ni], a4[mi], a5[mi], a0[mi], a1[mi], b0[ni], b2[ni]);
        }

        // wait only for chunk i+1's B (issued last iteration); i+2 stays in flight
        if (i + 1 < NCHUNK) CP_WAIT(1);
        __syncthreads();
    }

    // ---------- write logits to smem [128][LPAD] ----------
#pragma unroll
    for (int mi = 0; mi < 2; mi++)
#pragma unroll
        for (int ni = 0; ni < 4; ni++) {
            int row = warpM * 32 + mi * 16 + quad;
            int col = warpN * 32 + ni * 8 + 2 * qt;
            *(float2*)&Sf[row * LPAD + col]       = make_float2(acc[mi][ni][0], acc[mi][ni][1]);
            *(float2*)&Sf[(row + 8) * LPAD + col] = make_float2(acc[mi][ni][2], acc[mi][ni][3]);
        }
    __syncthreads();

    // ---------- per-token epilogue (threads 0..127) ----------
    const bool act = tid < BM;
    float v[E_EXP];
    float l1 = -1e30f, l2 = -1e30f, inv = 0.0f;
    int   i1 = 0, i2 = 0;
    if (act) {
        const float* row = &Sf[tid * LPAD];
#pragma unroll
        for (int j = 0; j < E_EXP / 4; j++) {
            float4 q = *(const float4*)&row[4 * j];
            v[4 * j] = q.x; v[4 * j + 1] = q.y; v[4 * j + 2] = q.z; v[4 * j + 3] = q.w;
        }
#pragma unroll
        for (int e = 0; e < E_EXP; e++) {
            float x = v[e];
            if (x > l1)      { l2 = l1; i2 = i1; l1 = x; i1 = e; }
            else if (x > l2) { l2 = x;  i2 = e; }
        }
        float ssum = 0.0f;
#pragma unroll
        for (int e = 0; e < E_EXP; e++) { float p = __expf(v[e] - l1); ssum += p; v[e] = p; }
        inv = 1.0f / ssum;
    }
    __syncthreads();
    if (act) {
#pragma unroll
        for (int j = 0; j < E_EXP / 4; j++) {
            float4 q = make_float4(v[4 * j] * inv, v[4 * j + 1] * inv, v[4 * j + 2] * inv, v[4 * j + 3] * inv);
            *(float4*)&Sf[tid * E_EXP + 4 * j] = q;
        }
        float e2 = __expf(l2 - l1);
        float dn = 1.0f / (1.0f + e2);
        int gm = m0 + tid;
        out[2 * gm + 0] = (float)i1;
        out[2 * gm + 1] = (float)i2;
        out[2 * T_TOK + 2 * gm + 0] = dn;
        out[2 * T_TOK + 2 * gm + 1] = e2 * dn;
        atomicAdd(&sCnt[i1], 1);
    }
    __syncthreads();

    // ---------- per-expert partials + fused aux ----------
    if (tid < E_EXP) {
        float s = 0.0f;
#pragma unroll 8
        for (int m = 0; m < BM; m++) s += Sf[m * E_EXP + tid];
        g_psum[bid * E_EXP + tid] = s;
        g_pcnt[bid * E_EXP + tid] = (float)sCnt[tid];
    }
    __threadfence();
    __syncthreads();

    if (tid == 0) s_last = (atomicInc(&g_done, NCTA - 1) == NCTA - 1) ? 1u : 0u;
    __syncthreads();

    if (s_last) {
        __threadfence();
        if (tid < E_EXP) {
            float a = 0.0f, cn = 0.0f;
#pragma unroll 8
            for (int b = 0; b < NCTA; b++) {
                a  += __ldcg(&g_psum[b * E_EXP + tid]);
                cn += __ldcg(&g_pcnt[b * E_EXP + tid]);
            }
            float invT = 1.0f / (float)T_TOK;
            sRed[tid] = (cn * invT) * (a * invT);
        }
        __syncthreads();
        if (tid < 32) {
            float vv = sRed[tid] + sRed[tid + 32];
#pragma unroll
            for (int o = 16; o > 0; o >>= 1) vv += __shfl_xor_sync(0xFFFFFFFF, vv, o);
            if (tid == 0) out[4 * T_TOK] = (float)E_EXP * AUX_W * vv;
        }
    }
}

extern "C" void kernel_launch(void* const* d_in, const int* in_sizes, int n_in,
                              void* d_out, int out_size) {
    const float* X = (const float*)d_in[0];
    const float* W = (const float*)d_in[1];
    float* out = (float*)d_out;

    prep_kernel<<<256, 256>>>(W);
    cudaFuncSetAttribute(router_kernel, cudaFuncAttributeMaxDynamicSharedMemorySize, DYN_SMEM);
    router_kernel<<<NCTA, THREADS, DYN_SMEM>>>(X, W, out);
}

// round 12
// speedup vs baseline: 1.5703x; 1.0532x over previous
#include <cuda_runtime.h>
#include <cstdint>

// ---------------- problem constants ----------------
#define T_TOK   16384
#define D_DIM   2048
#define E_EXP   64
#define AUX_W   0.01f

#define BM      128
#define BK      32
#define NCHUNK  (D_DIM / BK)      // 64
#define GCH     (NCHUNK / 2)      // 32 chunks per k-group
#define THREADS 512
#define NCTA    (T_TOK / BM)      // 128
#define LPAD    68

// smem stage layout (bytes). bf16 planes, row stride 80 B
// A planes: 128 rows x 80 = 10240 each; B planes: 64 rows x 80 = 5120 each
#define AP0     0
#define AP1     10240
#define AP2     20480
#define BP0     30720
#define BP1     35840
#define BP2     40960
#define STG_B   46080
#define DYN_SMEM (4 * STG_B)      // 184320 (2 groups x 2 stages)

// ---------------- global scratch ----------------
__device__ uint32_t g_Wb0[E_EXP * D_DIM / 2];
__device__ uint32_t g_Wb1[E_EXP * D_DIM / 2];
__device__ uint32_t g_Wb2[E_EXP * D_DIM / 2];
__device__ float    g_psum[NCTA * E_EXP];
__device__ float    g_pcnt[NCTA * E_EXP];
__device__ unsigned g_done = 0;

// ---------------- helpers ----------------
__device__ __forceinline__ uint32_t smem_u32(const void* p) {
    uint32_t a;
    asm("{ .reg .u64 t; cvta.to.shared.u64 t, %1; cvt.u32.u64 %0, t; }" : "=r"(a) : "l"(p));
    return a;
}
// round-to-nearest 3-way bf16 split of a float pair (x = even k -> low half)
__device__ __forceinline__ void split3_pair(float x, float y, uint32_t& p0, uint32_t& p1, uint32_t& p2) {
    asm("cvt.rn.bf16x2.f32 %0, %1, %2;" : "=r"(p0) : "f"(y), "f"(x));
    float x0 = __uint_as_float(p0 << 16);
    float y0 = __uint_as_float(p0 & 0xFFFF0000u);
    float xr1 = x - x0;
    float yr1 = y - y0;
    asm("cvt.rn.bf16x2.f32 %0, %1, %2;" : "=r"(p1) : "f"(yr1), "f"(xr1));
    float x1 = __uint_as_float(p1 << 16);
    float y1 = __uint_as_float(p1 & 0xFFFF0000u);
    float xr2 = xr1 - x1;
    float yr2 = yr1 - y1;
    asm("cvt.rn.bf16x2.f32 %0, %1, %2;" : "=r"(p2) : "f"(yr2), "f"(xr2));
}
__device__ __forceinline__ void sts64(uint32_t addr, uint32_t a, uint32_t b) {
    asm volatile("st.shared.v2.b32 [%0], {%1, %2};" :: "r"(addr), "r"(a), "r"(b) : "memory");
}
__device__ __forceinline__ uint32_t lds32(uint32_t addr) {
    uint32_t r;
    asm volatile("ld.shared.b32 %0, [%1];" : "=r"(r) : "r"(addr));
    return r;
}
#define CP_ASYNC16(saddr, gptr) \
    asm volatile("cp.async.cg.shared.global [%0], [%1], 16;" :: "r"(saddr), "l"(gptr) : "memory")
#define CP_COMMIT() asm volatile("cp.async.commit_group;" ::: "memory")
#define CP_WAIT0()  asm volatile("cp.async.wait_group 0;" ::: "memory")
#define BAR_GRP(id) asm volatile("bar.sync %0, 256;" :: "r"(id) : "memory")

#define MMA_BF16(c, a0, a1, a2, a3, b0, b1) \
    asm volatile("mma.sync.aligned.m16n8k16.row.col.f32.bf16.bf16.f32 " \
        "{%0,%1,%2,%3}, {%4,%5,%6,%7}, {%8,%9}, {%0,%1,%2,%3};" \
        : "+f"((c)[0]), "+f"((c)[1]), "+f"((c)[2]), "+f"((c)[3]) \
        : "r"(a0), "r"(a1), "r"(a2), "r"(a3), "r"(b0), "r"(b1))

// ---------------- W pre-split kernel ----------------
__global__ __launch_bounds__(256) void prep_kernel(const float* __restrict__ W) {
    int i = blockIdx.x * 256 + threadIdx.x;     // pair index
    float2 v = ((const float2*)W)[i];
    uint32_t p0, p1, p2;
    split3_pair(v.x, v.y, p0, p1, p2);
    g_Wb0[i] = p0;
    g_Wb1[i] = p1;
    g_Wb2[i] = p2;
}

// ---------------- router ----------------
extern __shared__ __align__(16) float Sf[];

__global__ __launch_bounds__(THREADS, 1) void router_kernel(
    const float* __restrict__ X,
    const float* __restrict__ W,
    float* __restrict__ out)
{
    __shared__ int   sCnt[E_EXP];
    __shared__ float sRed[E_EXP];
    __shared__ unsigned s_last;

    const int tid   = threadIdx.x;
    const int lane  = tid & 31;
    const int wrp   = tid >> 5;       // 0..15
    const int g     = wrp >> 3;       // k-group 0/1
    const int gw    = wrp & 7;        // warp within group
    const int gt    = tid & 255;      // thread within group
    const int warpM = gw >> 1;        // 0..3 -> rows [warpM*32,+32)
    const int warpN = gw & 1;         // 0..1 -> cols [warpN*32,+32)
    const int quad  = lane >> 2;
    const int qt    = lane & 3;
    const int bid   = blockIdx.x;
    const int m0    = bid * BM;

    if (tid < E_EXP) sCnt[tid] = 0;

    const float* Xp = X + (size_t)m0 * D_DIM;
    const uint32_t sb = smem_u32(Sf);
    const uint32_t gbase = sb + (uint32_t)(g * 2) * STG_B;   // this group's 2 stages

    // A slots within group: idx = gt + r*256 (r<4): row = idx>>3, c4 = idx&7
    int ar[4], ac[4];
#pragma unroll
    for (int r = 0; r < 4; r++) { int s = gt + r * 256; ar[r] = s >> 3; ac[r] = s & 7; }
    // B cp slots within group: idx = gt + r*256 (r<3): plane = idx>>8, n = (idx&255)>>2, c16 = idx&3
    int bp[3], bn[3], bc[3];
#pragma unroll
    for (int r = 0; r < 3; r++) { int s = gt + r * 256; bp[r] = s >> 8; bn[r] = (s & 255) >> 2; bc[r] = s & 3; }

    float4 xv[4];
    auto ldgx = [&](int j) {                   // j = group-local chunk
        const int kt = (g * GCH + j) * BK;
#pragma unroll
        for (int r = 0; r < 4; r++) xv[r] = *(const float4*)(Xp + (size_t)ar[r] * D_DIM + kt + ac[r] * 4);
    };
    auto stsa = [&](int s) {
        const uint32_t st = gbase + (uint32_t)s * STG_B;
#pragma unroll
        for (int r = 0; r < 4; r++) {
            uint32_t base = st + (uint32_t)ar[r] * 80u + (uint32_t)ac[r] * 8u;
            uint32_t q00, q01, q02, q10, q11, q12;
            split3_pair(xv[r].x, xv[r].y, q00, q01, q02);
            split3_pair(xv[r].z, xv[r].w, q10, q11, q12);
            sts64(base + AP0, q00, q10);
            sts64(base + AP1, q01, q11);
            sts64(base + AP2, q02, q12);
        }
    };
    auto cpb = [&](int j, int s) {
        const int c = g * GCH + j;
        const uint32_t st = gbase + (uint32_t)s * STG_B;
#pragma unroll
        for (int r = 0; r < 3; r++) {
            const uint32_t* gsrc =
                (bp[r] == 0 ? g_Wb0 : (bp[r] == 1 ? g_Wb1 : g_Wb2))
                + (size_t)bn[r] * (D_DIM / 2) + c * (BK / 2) + bc[r] * 4;
            uint32_t dst = st + BP0 + (uint32_t)bp[r] * 5120u + (uint32_t)bn[r] * 80u + (uint32_t)bc[r] * 16u;
            CP_ASYNC16(dst, gsrc);
        }
        CP_COMMIT();
    };

    float acc[2][4][4];
#pragma unroll
    for (int mi = 0; mi < 2; mi++)
#pragma unroll
        for (int ni = 0; ni < 4; ni++)
#pragma unroll
            for (int r = 0; r < 4; r++) acc[mi][ni][r] = 0.0f;

    // ---- prologue (per group, independent) ----
    ldgx(0);
    stsa(0);
    cpb(0, 0);
    ldgx(1);
    CP_WAIT0();
    BAR_GRP(g + 1);

    const uint32_t aRow = (uint32_t)(warpM * 32 + quad) * 80u + (uint32_t)qt * 4u;
    const uint32_t bRow = (uint32_t)(warpN * 32 + quad) * 80u + (uint32_t)qt * 4u + BP0;

#pragma unroll 1
    for (int j = 0; j < GCH; j++) {
        const int s = j & 1;
        const uint32_t st = gbase + (uint32_t)s * STG_B;

        if (j + 1 < GCH) { cpb(j + 1, s ^ 1); stsa(s ^ 1); }
        if (j + 2 < GCH) ldgx(j + 2);

        // consumer: 4 k8-groups of this chunk
#pragma unroll
        for (int kg = 0; kg < 4; kg++) {
            const uint32_t off = (uint32_t)kg * 16u;
            uint32_t a0[2], a1[2], a2[2], a3[2], a4[2], a5[2];
#pragma unroll
            for (int mi = 0; mi < 2; mi++) {
                uint32_t ab = st + aRow + (uint32_t)(mi * 16) * 80u + off;
                a0[mi] = lds32(ab + AP0);
                a1[mi] = lds32(ab + AP0 + 640u);
                a2[mi] = lds32(ab + AP1);
                a3[mi] = lds32(ab + AP1 + 640u);
                a4[mi] = lds32(ab + AP2);
                a5[mi] = lds32(ab + AP2 + 640u);
            }
            uint32_t b0[4], b1[4], b2[4];
#pragma unroll
            for (int ni = 0; ni < 4; ni++) {
                uint32_t bb = st + bRow + (uint32_t)(ni * 8) * 80u + off;
                b0[ni] = lds32(bb);
                b1[ni] = lds32(bb + 5120u);
                b2[ni] = lds32(bb + 10240u);
            }
#pragma unroll
            for (int mi = 0; mi < 2; mi++)
#pragma unroll
                for (int ni = 0; ni < 4; ni++)
                    MMA_BF16(acc[mi][ni], a0[mi], a1[mi], a2[mi], a3[mi], b0[ni], b1[ni]);
#pragma unroll
            for (int mi = 0; mi < 2; mi++)
#pragma unroll
                for (int ni = 0; ni < 4; ni++)
                    MMA_BF16(acc[mi][ni], a0[mi], a1[mi], a2[mi], a3[mi], b1[ni], b0[ni]);
#pragma unroll
            for (int mi = 0; mi < 2; mi++)
#pragma unroll
                for (int ni = 0; ni < 4; ni++)
                    MMA_BF16(acc[mi][ni], a4[mi], a5[mi], a0[mi], a1[mi], b0[ni], b2[ni]);
        }

        CP_WAIT0();
        BAR_GRP(g + 1);
    }

    // ---------- combine both groups' partial logits into Sf[128][LPAD] ----------
    __syncthreads();
    if (g == 1) {
#pragma unroll
        for (int mi = 0; mi < 2; mi++)
#pragma unroll
            for (int ni = 0; ni < 4; ni++) {
                int row = warpM * 32 + mi * 16 + quad;
                int col = warpN * 32 + ni * 8 + 2 * qt;
                *(float2*)&Sf[row * LPAD + col]       = make_float2(acc[mi][ni][0], acc[mi][ni][1]);
                *(float2*)&Sf[(row + 8) * LPAD + col] = make_float2(acc[mi][ni][2], acc[mi][ni][3]);
            }
    }
    __syncthreads();
    if (g == 0) {
#pragma unroll
        for (int mi = 0; mi < 2; mi++)
#pragma unroll
            for (int ni = 0; ni < 4; ni++) {
                int row = warpM * 32 + mi * 16 + quad;
                int col = warpN * 32 + ni * 8 + 2 * qt;
                float2 p0 = *(float2*)&Sf[row * LPAD + col];
                float2 p1 = *(float2*)&Sf[(row + 8) * LPAD + col];
                *(float2*)&Sf[row * LPAD + col]       = make_float2(p0.x + acc[mi][ni][0], p0.y + acc[mi][ni][1]);
                *(float2*)&Sf[(row + 8) * LPAD + col] = make_float2(p1.x + acc[mi][ni][2], p1.y + acc[mi][ni][3]);
            }
    }
    __syncthreads();

    // ---------- per-token epilogue (threads 0..127) ----------
    const bool act = tid < BM;
    float v[E_EXP];
    float l1 = -1e30f, l2 = -1e30f, inv = 0.0f;
    int   i1 = 0, i2 = 0;
    if (act) {
        const float* row = &Sf[tid * LPAD];
#pragma unroll
        for (int j = 0; j < E_EXP / 4; j++) {
            float4 q = *(const float4*)&row[4 * j];
            v[4 * j] = q.x; v[4 * j + 1] = q.y; v[4 * j + 2] = q.z; v[4 * j + 3] = q.w;
        }
#pragma unroll
        for (int e = 0; e < E_EXP; e++) {
            float x = v[e];
            if (x > l1)      { l2 = l1; i2 = i1; l1 = x; i1 = e; }
            else if (x > l2) { l2 = x;  i2 = e; }
        }
        float ssum = 0.0f;
#pragma unroll
        for (int e = 0; e < E_EXP; e++) { float p = __expf(v[e] - l1); ssum += p; v[e] = p; }
        inv = 1.0f / ssum;
    }
    __syncthreads();
    if (act) {
#pragma unroll
        for (int j = 0; j < E_EXP / 4; j++) {
            float4 q = make_float4(v[4 * j] * inv, v[4 * j + 1] * inv, v[4 * j + 2] * inv, v[4 * j + 3] * inv);
            *(float4*)&Sf[tid * E_EXP + 4 * j] = q;
        }
        float e2 = __expf(l2 - l1);
        float dn = 1.0f / (1.0f + e2);
        int gm = m0 + tid;
        out[2 * gm + 0] = (float)i1;
        out[2 * gm + 1] = (float)i2;
        out[2 * T_TOK + 2 * gm + 0] = dn;
        out[2 * T_TOK + 2 * gm + 1] = e2 * dn;
        atomicAdd(&sCnt[i1], 1);
    }
    __syncthreads();

    // ---------- per-expert partials + fused aux ----------
    if (tid < E_EXP) {
        float s = 0.0f;
#pragma unroll 8
        for (int m = 0; m < BM; m++) s += Sf[m * E_EXP + tid];
        g_psum[bid * E_EXP + tid] = s;
        g_pcnt[bid * E_EXP + tid] = (float)sCnt[tid];
    }
    __threadfence();
    __syncthreads();

    if (tid == 0) s_last = (atomicInc(&g_done, NCTA - 1) == NCTA - 1) ? 1u : 0u;
    __syncthreads();

    if (s_last) {
        __threadfence();
        if (tid < E_EXP) {
            float a = 0.0f, cn = 0.0f;
#pragma unroll 8
            for (int b = 0; b < NCTA; b++) {
                a  += __ldcg(&g_psum[b * E_EXP + tid]);
                cn += __ldcg(&g_pcnt[b * E_EXP + tid]);
            }
            float invT = 1.0f / (float)T_TOK;
            sRed[tid] = (cn * invT) * (a * invT);
        }
        __syncthreads();
        if (tid < 32) {
            float vv = sRed[tid] + sRed[tid + 32];
#pragma unroll
            for (int o = 16; o > 0; o >>= 1) vv += __shfl_xor_sync(0xFFFFFFFF, vv, o);
            if (tid == 0) out[4 * T_TOK] = (float)E_EXP * AUX_W * vv;
        }
    }
}

extern "C" void kernel_launch(void* const* d_in, const int* in_sizes, int n_in,
                              void* d_out, int out_size) {
    const float* X = (const float*)d_in[0];
    const float* W = (const float*)d_in[1];
    float* out = (float*)d_out;

    prep_kernel<<<256, 256>>>(W);
    cudaFuncSetAttribute(router_kernel, cudaFuncAttributeMaxDynamicSharedMemorySize, DYN_SMEM);
    router_kernel<<<NCTA, THREADS, DYN_SMEM>>>(X, W, out);
}